// round 5
// baseline (speedup 1.0000x reference)
#include <cuda_runtime.h>
#include <cuda_fp16.h>
#include <cstdint>
#include <math.h>

#define BSZ 8
#define NPTS 2048
#define KNN 20
#define EPS 1e-5f
#define SLOPE 0.2f

// ---------------- scratch (device globals) ----------------
__device__ float g_d2[BSZ * NPTS];
__device__ int   g_idx[BSZ * NPTS * KNN];
__device__ float g_YZ[(long)BSZ * NPTS * 512];
__device__ float g_xc[(long)BSZ * NPTS * 512];
__device__ float g_weff[512 * 128];
__device__ float g_pmax[128 * 1024];
__device__ float g_psum[128 * 1024];
__device__ float g_g[BSZ * 2048];
__device__ float g_h1[BSZ * 512];
__device__ float g_h2[BSZ * 256];
__device__ __align__(16) unsigned short g_Xh[(long)BSZ * NPTS * 128];
__device__ __align__(16) unsigned short g_Xl[(long)BSZ * NPTS * 128];
__device__ __align__(16) unsigned short g_XCh[(long)BSZ * NPTS * 512];
__device__ __align__(16) unsigned short g_XCl[(long)BSZ * NPTS * 512];
__device__ __align__(16) unsigned short g_W5h[1024 * 512];
__device__ __align__(16) unsigned short g_W5l[1024 * 512];
__device__ __align__(16) unsigned short g_Wh[512 * 128];
__device__ __align__(16) unsigned short g_Wl[512 * 128];

__device__ __forceinline__ uint32_t smem_u32(const void* p) {
    uint32_t a;
    asm("{ .reg .u64 t; cvta.to.shared.u64 t, %1; cvt.u32.u64 %0, t; }" : "=r"(a) : "l"(p));
    return a;
}

#define LDSM4(f, addr) \
    asm volatile("ldmatrix.sync.aligned.m8n8.x4.shared.b16 {%0,%1,%2,%3}, [%4];" \
                 : "=r"((f)[0]), "=r"((f)[1]), "=r"((f)[2]), "=r"((f)[3]) : "r"(addr))

#define MMA16816(c, a, b0, b1) \
    asm volatile("mma.sync.aligned.m16n8k16.row.col.f32.f16.f16.f32 " \
                 "{%0,%1,%2,%3}, {%4,%5,%6,%7}, {%8,%9}, {%0,%1,%2,%3};" \
                 : "+f"((c)[0]), "+f"((c)[1]), "+f"((c)[2]), "+f"((c)[3]) \
                 : "r"((a)[0]), "r"((a)[1]), "r"((a)[2]), "r"((a)[3]), "r"(b0), "r"(b1))

// ======================= fused KNN: scores + top-20 =======================
// One block per (row-block of 128, batch). K==3: direct fp32 scores.
// K in {64,128}: HMMA split-fp16 (hh+hl+lh). Selection: 2 lanes per row,
// register top-20 each over half the columns, merged at the end.
// Dynamic smem: score tile 128*129 f32 | d2c 128 f32 | (K==3: col xyz 384 f32)
//               (K>3: Ah|Al|Bh|Bl fp16 tiles, 128*K each)
#define SC_FLOATS (128 * 129)
#define DYN_OFF ((SC_FLOATS + 128) * 4)

__global__ __launch_bounds__(256, 1) void knn_fused(
        const float* __restrict__ xf,
        const unsigned short* __restrict__ Xh0, const unsigned short* __restrict__ Xl0,
        const float* __restrict__ d2g,
        int K, int* __restrict__ idxo) {
    extern __shared__ __align__(16) char smem[];
    float* sc = (float*)smem;
    float* d2c = sc + SC_FLOATS;
    float* colx = d2c + 128;  // K==3 only (3*128 floats)

    int b = blockIdx.y, rb = blockIdx.x;
    int tid = threadIdx.x, wid = tid >> 5, lane = tid & 31;
    int row_local = wid * 16 + (lane >> 1);
    int half = lane & 1;

    // register top-20 for this (row, half)
    float tv[KNN];
    int ti[KNN];
#pragma unroll
    for (int t = 0; t < KNN; t++) { tv[t] = -INFINITY; ti[t] = 0x7fffffff; }
    float thr = -INFINITY;
    int minp = 0, miid = 0x7fffffff;

#define TOPK_UPD(s_, id_) do { \
    float s__ = (s_); int id__ = (id_); \
    if (s__ > thr) { \
        _Pragma("unroll") \
        for (int t = 0; t < KNN; t++) if (t == minp) { tv[t] = s__; ti[t] = id__; } \
        thr = tv[0]; minp = 0; miid = ti[0]; \
        _Pragma("unroll") \
        for (int t = 1; t < KNN; t++) { \
            bool lt = (tv[t] < thr) || (tv[t] == thr && ti[t] > miid); \
            if (lt) { thr = tv[t]; minp = t; miid = ti[t]; } \
        } \
    } } while (0)

    if (K == 3) {
        const float* xr = xf + ((long)b * NPTS + rb * 128 + row_local) * 3;
        float xr0 = xr[0], xr1 = xr[1], xr2 = xr[2];
        for (int ct = 0; ct < 16; ct++) {
            if (tid < 128) {
                const float* p = xf + ((long)b * NPTS + ct * 128 + tid) * 3;
                float cx = p[0], cy = p[1], cz = p[2];
                colx[tid] = cx; colx[128 + tid] = cy; colx[256 + tid] = cz;
                d2c[tid] = cx * cx + cy * cy + cz * cz;
            }
            __syncthreads();
#pragma unroll 4
            for (int j0 = 0; j0 < 64; j0++) {
                int j = half * 64 + j0;
                float s = 2.f * (xr0 * colx[j] + xr1 * colx[128 + j] + xr2 * colx[256 + j]) - d2c[j];
                TOPK_UPD(s, ct * 128 + j);
            }
            __syncthreads();
        }
    } else {
        int K8 = K >> 3;                 // 16B chunks per row
        int nch = 128 * K8;              // chunks per tile
        int KB = K * 2;                  // bytes per row
        char* pAh = smem + DYN_OFF;
        char* pAl = pAh + 128 * KB;
        char* pBh = pAl + 128 * KB;
        char* pBl = pBh + 128 * KB;
        uint32_t uAh = smem_u32(pAh), uAl = smem_u32(pAl);
        uint32_t uBh = smem_u32(pBh), uBl = smem_u32(pBl);

        // load A rows once
        const unsigned short* ArH = Xh0 + ((long)b * NPTS + rb * 128) * K;
        const unsigned short* ArL = Xl0 + ((long)b * NPTS + rb * 128) * K;
        for (int q = tid; q < nch; q += 256) {
            int r = q / K8, c = q % K8;
            int phys = r * KB + ((c ^ (r & 7)) << 4);
            *(uint4*)(pAh + phys) = *(const uint4*)(ArH + (long)r * K + c * 8);
            *(uint4*)(pAl + phys) = *(const uint4*)(ArL + (long)r * K + c * 8);
        }

        int wm = (wid >> 2) * 64, wn = (wid & 3) * 32;
        int a_r = lane & 15, a_kh = lane >> 4;
        int b_n = (lane & 7) + ((lane >> 4) << 3), b_kh = (lane >> 3) & 1;

        for (int ct = 0; ct < 16; ct++) {
            const unsigned short* BrH = Xh0 + ((long)b * NPTS + ct * 128) * K;
            const unsigned short* BrL = Xl0 + ((long)b * NPTS + ct * 128) * K;
            for (int q = tid; q < nch; q += 256) {
                int r = q / K8, c = q % K8;
                int phys = r * KB + ((c ^ (r & 7)) << 4);
                *(uint4*)(pBh + phys) = *(const uint4*)(BrH + (long)r * K + c * 8);
                *(uint4*)(pBl + phys) = *(const uint4*)(BrL + (long)r * K + c * 8);
            }
            if (tid < 128) d2c[tid] = d2g[b * NPTS + ct * 128 + tid];
            __syncthreads();

            float acc[4][4][4] = {};
            int nkk = K >> 4;
            for (int kk = 0; kk < nkk; kk++) {
                uint32_t af[4][4], bfh[2][4], bfl[2][4];
#pragma unroll
                for (int mt = 0; mt < 4; mt++) {
                    int row = wm + mt * 16 + a_r;
                    int ch = kk * 2 + a_kh;
                    LDSM4(af[mt], uAh + row * KB + ((ch ^ (row & 7)) << 4));
                }
#pragma unroll
                for (int g = 0; g < 2; g++) {
                    int row = wn + g * 16 + b_n;
                    int ch = kk * 2 + b_kh;
                    LDSM4(bfh[g], uBh + row * KB + ((ch ^ (row & 7)) << 4));
                }
#pragma unroll
                for (int mt = 0; mt < 4; mt++)
#pragma unroll
                    for (int nt = 0; nt < 4; nt++)
                        MMA16816(acc[mt][nt], af[mt], bfh[nt >> 1][(nt & 1) * 2], bfh[nt >> 1][(nt & 1) * 2 + 1]);
#pragma unroll
                for (int g = 0; g < 2; g++) {
                    int row = wn + g * 16 + b_n;
                    int ch = kk * 2 + b_kh;
                    LDSM4(bfl[g], uBl + row * KB + ((ch ^ (row & 7)) << 4));
                }
#pragma unroll
                for (int mt = 0; mt < 4; mt++)
#pragma unroll
                    for (int nt = 0; nt < 4; nt++)
                        MMA16816(acc[mt][nt], af[mt], bfl[nt >> 1][(nt & 1) * 2], bfl[nt >> 1][(nt & 1) * 2 + 1]);
#pragma unroll
                for (int mt = 0; mt < 4; mt++) {
                    int row = wm + mt * 16 + a_r;
                    int ch = kk * 2 + a_kh;
                    LDSM4(af[mt], uAl + row * KB + ((ch ^ (row & 7)) << 4));
                }
#pragma unroll
                for (int mt = 0; mt < 4; mt++)
#pragma unroll
                    for (int nt = 0; nt < 4; nt++)
                        MMA16816(acc[mt][nt], af[mt], bfh[nt >> 1][(nt & 1) * 2], bfh[nt >> 1][(nt & 1) * 2 + 1]);
            }
            // store scores to smem tile
#pragma unroll
            for (int mt = 0; mt < 4; mt++)
#pragma unroll
                for (int h = 0; h < 2; h++) {
                    int row = wm + mt * 16 + (lane >> 2) + h * 8;
#pragma unroll
                    for (int nt = 0; nt < 4; nt++) {
                        int col = wn + nt * 8 + (lane & 3) * 2;
                        sc[row * 129 + col] = acc[mt][nt][h * 2];
                        sc[row * 129 + col + 1] = acc[mt][nt][h * 2 + 1];
                    }
                }
            __syncthreads();
            // selection over this tile
#pragma unroll 4
            for (int j0 = 0; j0 < 64; j0++) {
                int j = half * 64 + j0;
                float s = 2.f * sc[row_local * 129 + j] - d2c[j];
                TOPK_UPD(s, ct * 128 + j);
            }
            __syncthreads();
        }
    }

    // ---- merge the two per-half lists per row ----
    float* mv = sc;                       // stride 41 per row
    int* mi = (int*)(sc + 128 * 41);
    {
        int base = row_local * 41 + half * 20;
#pragma unroll
        for (int t = 0; t < KNN; t++) { mv[base + t] = tv[t]; mi[base + t] = ti[t]; }
    }
    __syncthreads();
    if (tid < 128) {
        float* v = mv + tid * 41;
        int* ii = mi + tid * 41;
        long obase = ((long)b * NPTS + rb * 128 + tid) * KNN;
        for (int r = 0; r < KNN; r++) {
            float best = -INFINITY;
            int bp = 0, bi = 0x7fffffff;
#pragma unroll
            for (int t = 0; t < 40; t++) {
                float vv = v[t];
                int id = ii[t];
                if (vv > best || (vv == best && id < bi)) { best = vv; bp = t; bi = id; }
            }
            idxo[obase + r] = bi;
            v[bp] = -INFINITY;
        }
    }
}

// ======================= HMMA split-fp16 GEMM =======================
// mode 0: raw C write; mode 2: bn+leakyrelu C write; mode 3: bn+leakyrelu then
// per-block column max/sum partials (no C write).
__global__ __launch_bounds__(256) void gemm_mma(
        const unsigned short* __restrict__ Ah0, const unsigned short* __restrict__ Al0, long bsA,
        const unsigned short* __restrict__ Bh0, const unsigned short* __restrict__ Bl0, long bsB,
        float* __restrict__ Cm, int ldc, long bsC,
        int K, const float* __restrict__ bnp,
        int Nn, int mode,
        float* __restrict__ pmax, float* __restrict__ psum) {
    __shared__ __align__(16) char smA_h[8192];
    __shared__ __align__(16) char smA_l[8192];
    __shared__ __align__(16) char smB_h[8192];
    __shared__ __align__(16) char smB_l[8192];
    __shared__ float redm[2][128];
    __shared__ float reds[2][128];

    int tid = threadIdx.x, wid = tid >> 5, lane = tid & 31;
    int bm = blockIdx.y * 128, bn = blockIdx.x * 128, z = blockIdx.z;

    const unsigned short* Ah = Ah0 + (long)z * bsA;
    const unsigned short* Al = Al0 + (long)z * bsA;
    const unsigned short* Bh = Bh0 + (long)z * bsB;
    const unsigned short* Bl = Bl0 + (long)z * bsB;
    float* Cb = Cm + (long)z * bsC;

    int wm = (wid >> 2) * 64, wn = (wid & 3) * 32;
    int a_r = lane & 15, a_kh = lane >> 4;
    int b_n = (lane & 7) + ((lane >> 4) << 3), b_kh = (lane >> 3) & 1;

    uint32_t sAh = smem_u32(smA_h), sAl = smem_u32(smA_l);
    uint32_t sBh = smem_u32(smB_h), sBl = smem_u32(smB_l);

    float acc[4][4][4] = {};

    for (int k0 = 0; k0 < K; k0 += 32) {
#pragma unroll
        for (int i = 0; i < 2; i++) {
            int q = tid + i * 256;
            int r = q >> 2, ci = q & 3;
            int phys = r * 64 + ((ci ^ ((r >> 1) & 3)) * 16);
            long ga = (long)(bm + r) * K + k0 + ci * 8;
            long gb = (long)(bn + r) * K + k0 + ci * 8;
            *(uint4*)(smA_h + phys) = *(const uint4*)(Ah + ga);
            *(uint4*)(smA_l + phys) = *(const uint4*)(Al + ga);
            *(uint4*)(smB_h + phys) = *(const uint4*)(Bh + gb);
            *(uint4*)(smB_l + phys) = *(const uint4*)(Bl + gb);
        }
        __syncthreads();
#pragma unroll
        for (int s = 0; s < 2; s++) {
            uint32_t af[4][4], bfh[2][4], bfl[2][4];
#pragma unroll
            for (int mt = 0; mt < 4; mt++) {
                int row = wm + mt * 16 + a_r;
                int ch = 2 * s + a_kh;
                LDSM4(af[mt], sAh + row * 64 + ((ch ^ ((row >> 1) & 3)) * 16));
            }
#pragma unroll
            for (int g = 0; g < 2; g++) {
                int row = wn + g * 16 + b_n;
                int ch = 2 * s + b_kh;
                LDSM4(bfh[g], sBh + row * 64 + ((ch ^ ((row >> 1) & 3)) * 16));
            }
#pragma unroll
            for (int mt = 0; mt < 4; mt++)
#pragma unroll
                for (int nt = 0; nt < 4; nt++)
                    MMA16816(acc[mt][nt], af[mt], bfh[nt >> 1][(nt & 1) * 2], bfh[nt >> 1][(nt & 1) * 2 + 1]);
#pragma unroll
            for (int g = 0; g < 2; g++) {
                int row = wn + g * 16 + b_n;
                int ch = 2 * s + b_kh;
                LDSM4(bfl[g], sBl + row * 64 + ((ch ^ ((row >> 1) & 3)) * 16));
            }
#pragma unroll
            for (int mt = 0; mt < 4; mt++)
#pragma unroll
                for (int nt = 0; nt < 4; nt++)
                    MMA16816(acc[mt][nt], af[mt], bfl[nt >> 1][(nt & 1) * 2], bfl[nt >> 1][(nt & 1) * 2 + 1]);
#pragma unroll
            for (int mt = 0; mt < 4; mt++) {
                int row = wm + mt * 16 + a_r;
                int ch = 2 * s + a_kh;
                LDSM4(af[mt], sAl + row * 64 + ((ch ^ ((row >> 1) & 3)) * 16));
            }
#pragma unroll
            for (int mt = 0; mt < 4; mt++)
#pragma unroll
                for (int nt = 0; nt < 4; nt++)
                    MMA16816(acc[mt][nt], af[mt], bfh[nt >> 1][(nt & 1) * 2], bfh[nt >> 1][(nt & 1) * 2 + 1]);
        }
        __syncthreads();
    }

    if (mode == 3) {
        float cmax[8], csum[8];
#pragma unroll
        for (int q = 0; q < 8; q++) { cmax[q] = -INFINITY; csum[q] = 0.f; }
#pragma unroll
        for (int mt = 0; mt < 4; mt++)
#pragma unroll
            for (int h = 0; h < 2; h++)
#pragma unroll
                for (int nt = 0; nt < 4; nt++)
#pragma unroll
                    for (int j = 0; j < 2; j++) {
                        int col = bn + wn + nt * 8 + (lane & 3) * 2 + j;
                        float v = acc[mt][nt][h * 2 + j];
                        float gg = bnp[col], be = bnp[Nn + col];
                        float mm = bnp[2 * Nn + col], vv = bnp[3 * Nn + col];
                        v = (v - mm) * (gg * rsqrtf(vv + EPS)) + be;
                        v = v > 0.f ? v : SLOPE * v;
                        int q = nt * 2 + j;
                        cmax[q] = fmaxf(cmax[q], v);
                        csum[q] += v;
                    }
#pragma unroll
        for (int q = 0; q < 8; q++) {
#pragma unroll
            for (int off = 4; off < 32; off <<= 1) {
                cmax[q] = fmaxf(cmax[q], __shfl_xor_sync(0xffffffffu, cmax[q], off));
                csum[q] += __shfl_xor_sync(0xffffffffu, csum[q], off);
            }
        }
        if ((lane >> 2) == 0) {
            int g = wid >> 2;
#pragma unroll
            for (int nt = 0; nt < 4; nt++)
#pragma unroll
                for (int j = 0; j < 2; j++) {
                    int cl = wn + nt * 8 + (lane & 3) * 2 + j;
                    redm[g][cl] = cmax[nt * 2 + j];
                    reds[g][cl] = csum[nt * 2 + j];
                }
        }
        __syncthreads();
        if (tid < 128) {
            float m = fmaxf(redm[0][tid], redm[1][tid]);
            float s = reds[0][tid] + reds[1][tid];
            pmax[(long)blockIdx.y * 1024 + bn + tid] = m;
            psum[(long)blockIdx.y * 1024 + bn + tid] = s;
        }
        return;
    }

#pragma unroll
    for (int mt = 0; mt < 4; mt++) {
        int r0 = bm + wm + mt * 16 + (lane >> 2);
#pragma unroll
        for (int h = 0; h < 2; h++) {
            int row = r0 + h * 8;
#pragma unroll
            for (int nt = 0; nt < 4; nt++) {
                int col = bn + wn + nt * 8 + (lane & 3) * 2;
                float v0 = acc[mt][nt][h * 2];
                float v1 = acc[mt][nt][h * 2 + 1];
                if (mode == 2) {
                    float gg = bnp[col], be = bnp[Nn + col];
                    float mm = bnp[2 * Nn + col], vv = bnp[3 * Nn + col];
                    v0 = (v0 - mm) * (gg * rsqrtf(vv + EPS)) + be;
                    v0 = v0 > 0.f ? v0 : SLOPE * v0;
                    gg = bnp[col + 1]; be = bnp[Nn + col + 1];
                    mm = bnp[2 * Nn + col + 1]; vv = bnp[3 * Nn + col + 1];
                    v1 = (v1 - mm) * (gg * rsqrtf(vv + EPS)) + be;
                    v1 = v1 > 0.f ? v1 : SLOPE * v1;
                }
                *(float2*)&Cb[(long)row * ldc + col] = make_float2(v0, v1);
            }
        }
    }
}

// ======================= pool reduce =======================
__global__ void pool_reduce(const float* __restrict__ pmax, const float* __restrict__ psum,
                            float* __restrict__ gb) {
    int c = blockIdx.x * 256 + threadIdx.x;
    int b = blockIdx.y;
    float m = -INFINITY, s = 0.f;
#pragma unroll
    for (int i = 0; i < 16; i++) {
        int by = b * 16 + i;
        m = fmaxf(m, pmax[(long)by * 1024 + c]);
        s += psum[(long)by * 1024 + c];
    }
    gb[b * 2048 + c] = m;
    gb[b * 2048 + 1024 + c] = s * (1.0f / NPTS);
}

// ======================= fp32 -> fp16 hi/lo split =======================
__global__ void split_kernel(const float* __restrict__ src, int ld, int C, int rows,
                             unsigned short* __restrict__ hi, unsigned short* __restrict__ lo) {
    long i = (long)blockIdx.x * blockDim.x + threadIdx.x;
    if (i >= (long)rows * C) return;
    int r = (int)(i / C), c = (int)(i % C);
    float v = src[(long)r * ld + c];
    __half h = __float2half_rn(v);
    __half l = __float2half_rn(v - __half2float(h));
    hi[i] = *(unsigned short*)&h;
    lo[i] = *(unsigned short*)&l;
}

__global__ void make_weff_split(const float* __restrict__ w, int O, int C,
                                unsigned short* __restrict__ hi, unsigned short* __restrict__ lo) {
    int i = blockIdx.x * blockDim.x + threadIdx.x;
    if (i >= 2 * O * C) return;
    int row = i / C, c = i % C;
    float v;
    if (row < O) v = w[row * 2 * C + c];
    else { int o = row - O; v = w[o * 2 * C + C + c] - w[o * 2 * C + c]; }
    __half h = __float2half_rn(v);
    __half l = __float2half_rn(v - __half2float(h));
    hi[i] = *(unsigned short*)&h;
    lo[i] = *(unsigned short*)&l;
}

// ======================= fp32 SIMT GEMM (layer 1 YZ only) =======================
#define BM 128
#define BN 128
#define BK 8
__global__ __launch_bounds__(256) void gemm_abT(
        const float* __restrict__ A, int lda,
        const float* __restrict__ Bm, int ldb,
        float* __restrict__ Cm, int ldc,
        int M, int Nn, int K) {
    __shared__ float As[BK][BM + 4];
    __shared__ float Bs[BK][BN + 4];

    int tid = threadIdx.x;
    int tx = tid & 15, ty = tid >> 4;
    int bm = blockIdx.y * BM, bn = blockIdx.x * BN;
    int lk = tid & 7, lm = tid >> 3;

    float ra[4], rb[4];
    float acc[8][8] = {};

#pragma unroll
    for (int i = 0; i < 4; i++) {
        int m = lm + i * 32;
        ra[i] = (lk < K) ? A[(long)(bm + m) * lda + lk] : 0.f;
        rb[i] = (lk < K) ? Bm[(long)(bn + m) * ldb + lk] : 0.f;
    }

    for (int k0 = 0; k0 < K; k0 += BK) {
#pragma unroll
        for (int i = 0; i < 4; i++) {
            As[lk][lm + i * 32] = ra[i];
            Bs[lk][lm + i * 32] = rb[i];
        }
        __syncthreads();
        int kn = k0 + BK;
        if (kn < K) {
#pragma unroll
            for (int i = 0; i < 4; i++) {
                int m = lm + i * 32;
                ra[i] = (kn + lk < K) ? A[(long)(bm + m) * lda + kn + lk] : 0.f;
                rb[i] = (kn + lk < K) ? Bm[(long)(bn + m) * ldb + kn + lk] : 0.f;
            }
        }
#pragma unroll
        for (int kk = 0; kk < BK; kk++) {
            float4 a0 = *(const float4*)&As[kk][ty * 4];
            float4 a1 = *(const float4*)&As[kk][64 + ty * 4];
            float4 b0 = *(const float4*)&Bs[kk][tx * 4];
            float4 b1 = *(const float4*)&Bs[kk][64 + tx * 4];
            float av[8] = {a0.x, a0.y, a0.z, a0.w, a1.x, a1.y, a1.z, a1.w};
            float bv[8] = {b0.x, b0.y, b0.z, b0.w, b1.x, b1.y, b1.z, b1.w};
#pragma unroll
            for (int i = 0; i < 8; i++)
#pragma unroll
                for (int j = 0; j < 8; j++) acc[i][j] += av[i] * bv[j];
        }
        __syncthreads();
    }

#pragma unroll
    for (int i = 0; i < 8; i++) {
        int m = bm + (i < 4 ? ty * 4 + i : 64 + ty * 4 + (i - 4));
#pragma unroll
        for (int j = 0; j < 8; j++) {
            int n_ = bn + (j < 4 ? tx * 4 + j : 64 + tx * 4 + (j - 4));
            Cm[(long)m * ldc + n_] = acc[i][j];
        }
    }
}

// ---------------- d2 ----------------
__global__ void d2_kernel(const float* __restrict__ X, int ldx, int C,
                          float* __restrict__ d2, int total) {
    int i = blockIdx.x * blockDim.x + threadIdx.x;
    if (i >= total) return;
    const float* xr = X + (long)i * ldx;
    float s = 0.f;
    for (int c = 0; c < C; c++) { float v = xr[c]; s += v * v; }
    d2[i] = s;
}

// ---------------- build effective edge weights (fp32, layer 1) ----------------
__global__ void make_weff(const float* __restrict__ w, int O, int C,
                          float* __restrict__ weff) {
    int i = blockIdx.x * blockDim.x + threadIdx.x;
    if (i >= 2 * O * C) return;
    int row = i / C, c = i % C;
    if (row < O) weff[i] = w[row * 2 * C + c];
    else {
        int o = row - O;
        weff[i] = w[o * 2 * C + C + c] - w[o * 2 * C + c];
    }
}

// ---------------- gather + max + bn + act ----------------
__global__ void gather_max(const float* __restrict__ YZ, int twoO,
                           const int* __restrict__ idxi,
                           const float* __restrict__ bnp,
                           float* __restrict__ out, int ldo, int O) {
    int n = blockIdx.x, b = blockIdx.y, o = threadIdx.x;
    __shared__ int si[KNN];
    if (o < KNN) si[o] = idxi[((long)b * NPTS + n) * KNN + o];
    __syncthreads();
    const float* Yb = YZ + (long)b * NPTS * twoO;
    float m = -INFINITY;
#pragma unroll 4
    for (int k = 0; k < KNN; k++) m = fmaxf(m, Yb[(long)si[k] * twoO + o]);
    float z = Yb[(long)n * twoO + O + o];
    float t = m + z;
    float gg = bnp[o], be = bnp[O + o], mm = bnp[2 * O + o], vv = bnp[3 * O + o];
    float v = (t - mm) * (gg * rsqrtf(vv + EPS)) + be;
    v = v > 0.f ? v : SLOPE * v;
    out[((long)b * NPTS + n) * ldo + o] = v;
}

// ---------------- small FC ----------------
__global__ void fc_kernel(const float* __restrict__ in, int K,
                          const float* __restrict__ W,
                          const float* __restrict__ bias,
                          const float* __restrict__ bnp, int useAct,
                          float* __restrict__ out, int O) {
    int o = blockIdx.x, b = blockIdx.y, t = threadIdx.x;
    const float* xr = in + (long)b * K;
    const float* wr = W + (long)o * K;
    float s = 0.f;
    for (int k = t; k < K; k += 128) s += xr[k] * wr[k];
    __shared__ float red[4];
#pragma unroll
    for (int off = 16; off; off >>= 1) s += __shfl_down_sync(0xffffffffu, s, off);
    if ((t & 31) == 0) red[t >> 5] = s;
    __syncthreads();
    if (t == 0) {
        float tot = red[0] + red[1] + red[2] + red[3];
        if (bias) tot += bias[o];
        if (bnp) {
            float gg = bnp[o], be = bnp[O + o], mm = bnp[2 * O + o], vv = bnp[3 * O + o];
            tot = (tot - mm) * (gg * rsqrtf(vv + EPS)) + be;
        }
        if (useAct) tot = tot > 0.f ? tot : SLOPE * tot;
        out[(long)b * O + o] = tot;
    }
}

extern "C" void kernel_launch(void* const* d_in, const int* in_sizes, int n_in,
                              void* d_out, int out_size) {
    const float* x   = (const float*)d_in[0];
    const float* w1  = (const float*)d_in[2];
    const float* w2  = (const float*)d_in[3];
    const float* w3  = (const float*)d_in[4];
    const float* w4  = (const float*)d_in[5];
    const float* w5  = (const float*)d_in[6];
    const float* wl1 = (const float*)d_in[7];
    const float* wl2 = (const float*)d_in[8];
    const float* bl2 = (const float*)d_in[9];
    const float* wl3 = (const float*)d_in[10];
    const float* bl3 = (const float*)d_in[11];
    const float* bn1 = (const float*)d_in[12];
    const float* bn2 = (const float*)d_in[13];
    const float* bn3 = (const float*)d_in[14];
    const float* bn4 = (const float*)d_in[15];
    const float* bn5 = (const float*)d_in[16];
    const float* bn6 = (const float*)d_in[17];
    const float* bn7 = (const float*)d_in[18];

    float *d2, *YZ, *xc, *weff, *pmax, *psum, *gb, *h1, *h2;
    int* idx;
    unsigned short *Xh, *Xl, *XCh, *XCl, *W5h, *W5l, *Wh, *Wl;
    cudaGetSymbolAddress((void**)&d2, g_d2);
    cudaGetSymbolAddress((void**)&idx, g_idx);
    cudaGetSymbolAddress((void**)&YZ, g_YZ);
    cudaGetSymbolAddress((void**)&xc, g_xc);
    cudaGetSymbolAddress((void**)&weff, g_weff);
    cudaGetSymbolAddress((void**)&pmax, g_pmax);
    cudaGetSymbolAddress((void**)&psum, g_psum);
    cudaGetSymbolAddress((void**)&gb, g_g);
    cudaGetSymbolAddress((void**)&h1, g_h1);
    cudaGetSymbolAddress((void**)&h2, g_h2);
    cudaGetSymbolAddress((void**)&Xh, g_Xh);
    cudaGetSymbolAddress((void**)&Xl, g_Xl);
    cudaGetSymbolAddress((void**)&XCh, g_XCh);
    cudaGetSymbolAddress((void**)&XCl, g_XCl);
    cudaGetSymbolAddress((void**)&W5h, g_W5h);
    cudaGetSymbolAddress((void**)&W5l, g_W5l);
    cudaGetSymbolAddress((void**)&Wh, g_Wh);
    cudaGetSymbolAddress((void**)&Wl, g_Wl);

    const int KNN_SMEM_MAX = DYN_OFF + 4 * 128 * 128 * 2;  // K=128 config
    cudaFuncSetAttribute(knn_fused, cudaFuncAttributeMaxDynamicSharedMemorySize, KNN_SMEM_MAX);

    const int TOTAL = BSZ * NPTS;  // 16384

    // ---------- layer 1 (exact fp32 scores; K=3) ----------
    {
        int smk3 = DYN_OFF + 384 * 4;
        knn_fused<<<dim3(16, BSZ), 256, smk3>>>(x, nullptr, nullptr, nullptr, 3, idx);
    }
    make_weff<<<(2 * 64 * 3 + 255) / 256, 256>>>(w1, 64, 3, weff);
    gemm_abT<<<dim3(1, TOTAL / BM, 1), 256>>>(x, 3, weff, 3, YZ, 128, TOTAL, 128, 3);
    gather_max<<<dim3(NPTS, BSZ), 64>>>(YZ, 128, idx, bn1, xc + 0, 512, 64);

    // ---------- layers 2-4 (HMMA fp16-split, fused knn) ----------
    struct L { int off, C, O; const float* w; const float* bn; };
    L Ls[3] = { {0, 64, 64, w2, bn2}, {64, 64, 128, w3, bn3}, {128, 128, 256, w4, bn4} };
    for (int l = 0; l < 3; l++) {
        const L& c = Ls[l];
        d2_kernel<<<TOTAL / 256, 256>>>(xc + c.off, 512, c.C, d2, TOTAL);
        split_kernel<<<(int)(((long)TOTAL * c.C + 255) / 256), 256>>>(
            xc + c.off, 512, c.C, TOTAL, Xh, Xl);
        int smk = DYN_OFF + 4 * 128 * c.C * 2;
        knn_fused<<<dim3(16, BSZ), 256, smk>>>(nullptr, Xh, Xl, d2, c.C, idx);
        make_weff_split<<<(2 * c.O * c.C + 255) / 256, 256>>>(c.w, c.O, c.C, Wh, Wl);
        gemm_mma<<<dim3(2 * c.O / 128, TOTAL / 128, 1), 256>>>(
            Xh, Xl, 0, Wh, Wl, 0,
            YZ, 2 * c.O, 0, c.C, nullptr, 2 * c.O, 0, nullptr, nullptr);
        int outoff = (l == 0) ? 64 : (l == 1) ? 128 : 256;
        gather_max<<<dim3(NPTS, BSZ), c.O>>>(YZ, 2 * c.O, idx, c.bn, xc + outoff, 512, c.O);
    }

    // ---------- x5 GEMM with fused pool partials ----------
    split_kernel<<<(int)(((long)TOTAL * 512 + 255) / 256), 256>>>(xc, 512, 512, TOTAL, XCh, XCl);
    split_kernel<<<(1024 * 512 + 255) / 256, 256>>>(w5, 512, 512, 1024, W5h, W5l);
    gemm_mma<<<dim3(8, TOTAL / 128, 1), 256>>>(
        XCh, XCl, 0, W5h, W5l, 0,
        nullptr, 1024, 0, 512, bn5, 1024, 3, pmax, psum);
    pool_reduce<<<dim3(4, BSZ), 256>>>(pmax, psum, gb);

    // ---------- FC stack ----------
    fc_kernel<<<dim3(512, BSZ), 128>>>(gb, 2048, wl1, nullptr, bn6, 1, h1, 512);
    fc_kernel<<<dim3(256, BSZ), 128>>>(h1, 512, wl2, bl2, bn7, 1, h2, 256);
    fc_kernel<<<dim3(40, BSZ), 128>>>(h2, 256, wl3, bl3, nullptr, 0, (float*)d_out, 40);
}

// round 6
// speedup vs baseline: 3.2500x; 3.2500x over previous
#include <cuda_runtime.h>
#include <cuda_fp16.h>
#include <cstdint>
#include <math.h>

#define BSZ 8
#define NPTS 2048
#define KNN 20
#define EPS 1e-5f
#define SLOPE 0.2f

// ---------------- scratch (device globals) ----------------
__device__ float g_S[(long)BSZ * NPTS * NPTS];
__device__ float g_d2[BSZ * NPTS];
__device__ int   g_idx[BSZ * NPTS * KNN];
__device__ float g_YZ[(long)BSZ * NPTS * 512];
__device__ float g_xc[(long)BSZ * NPTS * 512];
__device__ float g_weff[512 * 128];
__device__ float g_pmax[128 * 1024];
__device__ float g_psum[128 * 1024];
__device__ float g_g[BSZ * 2048];
__device__ float g_h1[BSZ * 512];
__device__ float g_h2[BSZ * 256];
__device__ __align__(16) unsigned short g_Xh[(long)BSZ * NPTS * 128];
__device__ __align__(16) unsigned short g_Xl[(long)BSZ * NPTS * 128];
__device__ __align__(16) unsigned short g_XCh[(long)BSZ * NPTS * 512];
__device__ __align__(16) unsigned short g_XCl[(long)BSZ * NPTS * 512];
__device__ __align__(16) unsigned short g_W5h[1024 * 512];
__device__ __align__(16) unsigned short g_W5l[1024 * 512];
__device__ __align__(16) unsigned short g_Wh[512 * 128];
__device__ __align__(16) unsigned short g_Wl[512 * 128];

__device__ __forceinline__ uint32_t smem_u32(const void* p) {
    uint32_t a;
    asm("{ .reg .u64 t; cvta.to.shared.u64 t, %1; cvt.u32.u64 %0, t; }" : "=r"(a) : "l"(p));
    return a;
}

#define LDSM4(f, addr) \
    asm volatile("ldmatrix.sync.aligned.m8n8.x4.shared.b16 {%0,%1,%2,%3}, [%4];" \
                 : "=r"((f)[0]), "=r"((f)[1]), "=r"((f)[2]), "=r"((f)[3]) : "r"(addr))

#define MMA16816(c, a, b0, b1) \
    asm volatile("mma.sync.aligned.m16n8k16.row.col.f32.f16.f16.f32 " \
                 "{%0,%1,%2,%3}, {%4,%5,%6,%7}, {%8,%9}, {%0,%1,%2,%3};" \
                 : "+f"((c)[0]), "+f"((c)[1]), "+f"((c)[2]), "+f"((c)[3]) \
                 : "r"((a)[0]), "r"((a)[1]), "r"((a)[2]), "r"((a)[3]), "r"(b0), "r"(b1))

#define CPA16(dst, src) \
    asm volatile("cp.async.ca.shared.global [%0], [%1], 16;" :: "r"(dst), "l"(src))
#define CPA_COMMIT() asm volatile("cp.async.commit_group;" ::: "memory")
#define CPA_WAIT0() asm volatile("cp.async.wait_group 0;" ::: "memory")
#define CPA_WAIT1() asm volatile("cp.async.wait_group 1;" ::: "memory")

// ======================= HMMA split-fp16 GEMM (double-buffered cp.async) ===========
// C = A(MxK) * B(NxK)^T, fp16 hi/lo (hh+hl+lh, fp32 accum). Tile 128x128, K chunk 32.
// mode 0: raw; 1: 2v - d2[col]; 2: bn+leakyrelu; 3: bn+act + pooled partials only.
// dynamic smem: 2 buffers x 4 arrays x 8192B = 65536, + 2x2x128 floats = 67584.
#define GSM_BUF 8192
#define GSM_TOTAL (2 * 4 * GSM_BUF + 2048)

__global__ __launch_bounds__(256) void gemm_mma(
        const unsigned short* __restrict__ Ah0, const unsigned short* __restrict__ Al0, long bsA,
        const unsigned short* __restrict__ Bh0, const unsigned short* __restrict__ Bl0, long bsB,
        float* __restrict__ Cm, int ldc, long bsC,
        int K, const float* __restrict__ d2, const float* __restrict__ bnp,
        int Nn, int mode,
        float* __restrict__ pmax, float* __restrict__ psum) {
    extern __shared__ __align__(16) char dyn[];
    // layout: [buf][Ah|Al|Bh|Bl]
    float* redm = (float*)(dyn + 2 * 4 * GSM_BUF);
    float* reds = redm + 256;

    int tid = threadIdx.x, wid = tid >> 5, lane = tid & 31;
    int bm = blockIdx.y * 128, bn = blockIdx.x * 128, z = blockIdx.z;

    const unsigned short* Ah = Ah0 + (long)z * bsA;
    const unsigned short* Al = Al0 + (long)z * bsA;
    const unsigned short* Bh = Bh0 + (long)z * bsB;
    const unsigned short* Bl = Bl0 + (long)z * bsB;

    int wm = (wid >> 2) * 64, wn = (wid & 3) * 32;
    int a_r = lane & 15, a_kh = lane >> 4;
    int b_n = (lane & 7) + ((lane >> 4) << 3), b_kh = (lane >> 3) & 1;

    uint32_t ub = smem_u32(dyn);

    // per-thread load coords (2 transfers per array per chunk)
    int r0 = tid >> 2, ci0 = tid & 3;
    int r1 = (tid + 256) >> 2, ci1 = (tid + 256) & 3;
    int ph0 = r0 * 64 + ((ci0 ^ ((r0 >> 1) & 3)) * 16);
    int ph1 = r1 * 64 + ((ci1 ^ ((r1 >> 1) & 3)) * 16);

    int nch = K >> 5;

#define LOAD_CHUNK(bufi, k0_) do { \
    uint32_t o = ub + (bufi) * 4 * GSM_BUF; \
    long gA0 = (long)(bm + r0) * K + (k0_) + ci0 * 8; \
    long gA1 = (long)(bm + r1) * K + (k0_) + ci1 * 8; \
    long gB0 = (long)(bn + r0) * K + (k0_) + ci0 * 8; \
    long gB1 = (long)(bn + r1) * K + (k0_) + ci1 * 8; \
    CPA16(o + ph0, Ah + gA0);                 CPA16(o + ph1, Ah + gA1); \
    CPA16(o + GSM_BUF + ph0, Al + gA0);       CPA16(o + GSM_BUF + ph1, Al + gA1); \
    CPA16(o + 2 * GSM_BUF + ph0, Bh + gB0);   CPA16(o + 2 * GSM_BUF + ph1, Bh + gB1); \
    CPA16(o + 3 * GSM_BUF + ph0, Bl + gB0);   CPA16(o + 3 * GSM_BUF + ph1, Bl + gB1); \
    CPA_COMMIT(); \
} while (0)

    float acc[4][4][4] = {};

    LOAD_CHUNK(0, 0);
    for (int ch = 0; ch < nch; ch++) {
        if (ch + 1 < nch) {
            LOAD_CHUNK((ch + 1) & 1, (ch + 1) << 5);
            CPA_WAIT1();
        } else {
            CPA_WAIT0();
        }
        __syncthreads();
        uint32_t o = ub + (ch & 1) * 4 * GSM_BUF;
        uint32_t sAh = o, sAl = o + GSM_BUF, sBh = o + 2 * GSM_BUF, sBl = o + 3 * GSM_BUF;
#pragma unroll
        for (int s = 0; s < 2; s++) {
            uint32_t af[4][4], bfh[2][4], bfl[2][4];
#pragma unroll
            for (int mt = 0; mt < 4; mt++) {
                int row = wm + mt * 16 + a_r;
                int chh = 2 * s + a_kh;
                LDSM4(af[mt], sAh + row * 64 + ((chh ^ ((row >> 1) & 3)) * 16));
            }
#pragma unroll
            for (int g = 0; g < 2; g++) {
                int row = wn + g * 16 + b_n;
                int chh = 2 * s + b_kh;
                LDSM4(bfh[g], sBh + row * 64 + ((chh ^ ((row >> 1) & 3)) * 16));
            }
#pragma unroll
            for (int mt = 0; mt < 4; mt++)
#pragma unroll
                for (int nt = 0; nt < 4; nt++)
                    MMA16816(acc[mt][nt], af[mt], bfh[nt >> 1][(nt & 1) * 2], bfh[nt >> 1][(nt & 1) * 2 + 1]);
#pragma unroll
            for (int g = 0; g < 2; g++) {
                int row = wn + g * 16 + b_n;
                int chh = 2 * s + b_kh;
                LDSM4(bfl[g], sBl + row * 64 + ((chh ^ ((row >> 1) & 3)) * 16));
            }
#pragma unroll
            for (int mt = 0; mt < 4; mt++)
#pragma unroll
                for (int nt = 0; nt < 4; nt++)
                    MMA16816(acc[mt][nt], af[mt], bfl[nt >> 1][(nt & 1) * 2], bfl[nt >> 1][(nt & 1) * 2 + 1]);
#pragma unroll
            for (int mt = 0; mt < 4; mt++) {
                int row = wm + mt * 16 + a_r;
                int chh = 2 * s + a_kh;
                LDSM4(af[mt], sAl + row * 64 + ((chh ^ ((row >> 1) & 3)) * 16));
            }
#pragma unroll
            for (int mt = 0; mt < 4; mt++)
#pragma unroll
                for (int nt = 0; nt < 4; nt++)
                    MMA16816(acc[mt][nt], af[mt], bfh[nt >> 1][(nt & 1) * 2], bfh[nt >> 1][(nt & 1) * 2 + 1]);
        }
        __syncthreads();
    }

    if (mode == 3) {
        float cmax[8], csum[8];
#pragma unroll
        for (int q = 0; q < 8; q++) { cmax[q] = -INFINITY; csum[q] = 0.f; }
#pragma unroll
        for (int mt = 0; mt < 4; mt++)
#pragma unroll
            for (int h = 0; h < 2; h++)
#pragma unroll
                for (int nt = 0; nt < 4; nt++)
#pragma unroll
                    for (int j = 0; j < 2; j++) {
                        int col = bn + wn + nt * 8 + (lane & 3) * 2 + j;
                        float v = acc[mt][nt][h * 2 + j];
                        float gg = bnp[col], be = bnp[Nn + col];
                        float mm = bnp[2 * Nn + col], vv = bnp[3 * Nn + col];
                        v = (v - mm) * (gg * rsqrtf(vv + EPS)) + be;
                        v = v > 0.f ? v : SLOPE * v;
                        int q = nt * 2 + j;
                        cmax[q] = fmaxf(cmax[q], v);
                        csum[q] += v;
                    }
#pragma unroll
        for (int q = 0; q < 8; q++) {
#pragma unroll
            for (int off = 4; off < 32; off <<= 1) {
                cmax[q] = fmaxf(cmax[q], __shfl_xor_sync(0xffffffffu, cmax[q], off));
                csum[q] += __shfl_xor_sync(0xffffffffu, csum[q], off);
            }
        }
        if ((lane >> 2) == 0) {
            int g = wid >> 2;
#pragma unroll
            for (int nt = 0; nt < 4; nt++)
#pragma unroll
                for (int j = 0; j < 2; j++) {
                    int cl = wn + nt * 8 + (lane & 3) * 2 + j;
                    redm[g * 128 + cl] = cmax[nt * 2 + j];
                    reds[g * 128 + cl] = csum[nt * 2 + j];
                }
        }
        __syncthreads();
        if (tid < 128) {
            pmax[(long)blockIdx.y * 1024 + bn + tid] = fmaxf(redm[tid], redm[128 + tid]);
            psum[(long)blockIdx.y * 1024 + bn + tid] = reds[tid] + reds[128 + tid];
        }
        return;
    }

    float* Cb = Cm + (long)z * bsC;
#pragma unroll
    for (int mt = 0; mt < 4; mt++) {
        int rr = bm + wm + mt * 16 + (lane >> 2);
#pragma unroll
        for (int h = 0; h < 2; h++) {
            int row = rr + h * 8;
#pragma unroll
            for (int nt = 0; nt < 4; nt++) {
                int col = bn + wn + nt * 8 + (lane & 3) * 2;
                float v0 = acc[mt][nt][h * 2];
                float v1 = acc[mt][nt][h * 2 + 1];
                if (mode == 1) {
                    const float* dd = d2 + (long)z * NPTS;
                    v0 = 2.f * v0 - dd[col];
                    v1 = 2.f * v1 - dd[col + 1];
                } else if (mode == 2) {
                    float gg = bnp[col], be = bnp[Nn + col];
                    float mm = bnp[2 * Nn + col], vv = bnp[3 * Nn + col];
                    v0 = (v0 - mm) * (gg * rsqrtf(vv + EPS)) + be;
                    v0 = v0 > 0.f ? v0 : SLOPE * v0;
                    gg = bnp[col + 1]; be = bnp[Nn + col + 1];
                    mm = bnp[2 * Nn + col + 1]; vv = bnp[3 * Nn + col + 1];
                    v1 = (v1 - mm) * (gg * rsqrtf(vv + EPS)) + be;
                    v1 = v1 > 0.f ? v1 : SLOPE * v1;
                }
                *(float2*)&Cb[(long)row * ldc + col] = make_float2(v0, v1);
            }
        }
    }
}

// ======================= pool reduce =======================
__global__ void pool_reduce(const float* __restrict__ pmax, const float* __restrict__ psum,
                            float* __restrict__ gb) {
    int c = blockIdx.x * 256 + threadIdx.x;
    int b = blockIdx.y;
    float m = -INFINITY, s = 0.f;
#pragma unroll
    for (int i = 0; i < 16; i++) {
        int by = b * 16 + i;
        m = fmaxf(m, pmax[(long)by * 1024 + c]);
        s += psum[(long)by * 1024 + c];
    }
    gb[b * 2048 + c] = m;
    gb[b * 2048 + 1024 + c] = s * (1.0f / NPTS);
}

// ======================= fused d2 + fp16 hi/lo split =======================
// one warp per row; C multiple of 32 (64/128) or 512 for x5 (d2 skipped when null)
__global__ void d2split_kernel(const float* __restrict__ src, int ld, int C, int rows,
                               unsigned short* __restrict__ hi, unsigned short* __restrict__ lo,
                               float* __restrict__ d2) {
    int row = blockIdx.x * 8 + (threadIdx.x >> 5);
    int lane = threadIdx.x & 31;
    if (row >= rows) return;
    const float* xr = src + (long)row * ld;
    float s = 0.f;
    for (int c = lane; c < C; c += 32) {
        float v = xr[c];
        s += v * v;
        __half h = __float2half_rn(v);
        __half l = __float2half_rn(v - __half2float(h));
        hi[(long)row * C + c] = *(unsigned short*)&h;
        lo[(long)row * C + c] = *(unsigned short*)&l;
    }
    if (d2) {
#pragma unroll
        for (int o = 16; o; o >>= 1) s += __shfl_xor_sync(0xffffffffu, s, o);
        if (lane == 0) d2[row] = s;
    }
}

__global__ void make_weff_split(const float* __restrict__ w, int O, int C,
                                unsigned short* __restrict__ hi, unsigned short* __restrict__ lo) {
    int i = blockIdx.x * blockDim.x + threadIdx.x;
    if (i >= 2 * O * C) return;
    int row = i / C, c = i % C;
    float v;
    if (row < O) v = w[row * 2 * C + c];
    else { int o = row - O; v = w[o * 2 * C + C + c] - w[o * 2 * C + c]; }
    __half h = __float2half_rn(v);
    __half l = __float2half_rn(v - __half2float(h));
    hi[i] = *(unsigned short*)&h;
    lo[i] = *(unsigned short*)&l;
}

// ======================= fp32 SIMT GEMM (layer 1) =======================
#define BM 128
#define BN 128
#define BK 8
__global__ __launch_bounds__(256) void gemm_abT(
        const float* __restrict__ A, int lda, long bsA,
        const float* __restrict__ Bm, int ldb, long bsB,
        float* __restrict__ Cm, int ldc, long bsC,
        int M, int Nn, int K,
        const float* __restrict__ d2, long bsD2, int mode) {
    const float* Ab = A + (long)blockIdx.z * bsA;
    const float* Bb = Bm + (long)blockIdx.z * bsB;
    float* Cb = Cm + (long)blockIdx.z * bsC;

    __shared__ float As[BK][BM + 4];
    __shared__ float Bs[BK][BN + 4];

    int tid = threadIdx.x;
    int tx = tid & 15, ty = tid >> 4;
    int bm = blockIdx.y * BM, bn = blockIdx.x * BN;
    int lk = tid & 7, lm = tid >> 3;

    float ra[4], rb[4];
    float acc[8][8] = {};

#pragma unroll
    for (int i = 0; i < 4; i++) {
        int m = lm + i * 32;
        ra[i] = (lk < K) ? Ab[(long)(bm + m) * lda + lk] : 0.f;
        rb[i] = (lk < K) ? Bb[(long)(bn + m) * ldb + lk] : 0.f;
    }

    for (int k0 = 0; k0 < K; k0 += BK) {
#pragma unroll
        for (int i = 0; i < 4; i++) {
            As[lk][lm + i * 32] = ra[i];
            Bs[lk][lm + i * 32] = rb[i];
        }
        __syncthreads();
        int kn = k0 + BK;
        if (kn < K) {
#pragma unroll
            for (int i = 0; i < 4; i++) {
                int m = lm + i * 32;
                ra[i] = (kn + lk < K) ? Ab[(long)(bm + m) * lda + kn + lk] : 0.f;
                rb[i] = (kn + lk < K) ? Bb[(long)(bn + m) * ldb + kn + lk] : 0.f;
            }
        }
#pragma unroll
        for (int kk = 0; kk < BK; kk++) {
            float4 a0 = *(const float4*)&As[kk][ty * 4];
            float4 a1 = *(const float4*)&As[kk][64 + ty * 4];
            float4 b0 = *(const float4*)&Bs[kk][tx * 4];
            float4 b1 = *(const float4*)&Bs[kk][64 + tx * 4];
            float av[8] = {a0.x, a0.y, a0.z, a0.w, a1.x, a1.y, a1.z, a1.w};
            float bv[8] = {b0.x, b0.y, b0.z, b0.w, b1.x, b1.y, b1.z, b1.w};
#pragma unroll
            for (int i = 0; i < 8; i++)
#pragma unroll
                for (int j = 0; j < 8; j++) acc[i][j] += av[i] * bv[j];
        }
        __syncthreads();
    }

#pragma unroll
    for (int i = 0; i < 8; i++) {
        int m = bm + (i < 4 ? ty * 4 + i : 64 + ty * 4 + (i - 4));
#pragma unroll
        for (int j = 0; j < 8; j++) {
            int n_ = bn + (j < 4 ? tx * 4 + j : 64 + tx * 4 + (j - 4));
            float v = acc[i][j];
            if (mode == 1) v = 2.f * v - d2[(long)blockIdx.z * bsD2 + n_];
            Cb[(long)m * ldc + n_] = v;
        }
    }
}

// ---------------- d2 (layer 1) ----------------
__global__ void d2_kernel(const float* __restrict__ X, int ldx, int C,
                          float* __restrict__ d2, int total) {
    int i = blockIdx.x * blockDim.x + threadIdx.x;
    if (i >= total) return;
    const float* xr = X + (long)i * ldx;
    float s = 0.f;
    for (int c = 0; c < C; c++) { float v = xr[c]; s += v * v; }
    d2[i] = s;
}

// ---------------- top-k: one warp per row, register-resident ----------------
__global__ __launch_bounds__(256) void topk_kernel(const float* __restrict__ S,
                                                   int* __restrict__ idxo) {
    int warp = threadIdx.x >> 5, lane = threadIdx.x & 31;
    int row = blockIdx.x * 8 + warp;
    const float* s = S + (long)row * NPTS;

    float r[64];
#pragma unroll
    for (int j = 0; j < 64; j++) r[j] = s[j * 32 + lane];

    for (int it = 0; it < KNN; it++) {
        float best = -INFINITY;
        int bj = 0;
#pragma unroll
        for (int j = 0; j < 64; j++) {
            if (r[j] > best) { best = r[j]; bj = j; }
        }
        int bidx = bj * 32 + lane;
#pragma unroll
        for (int o = 16; o; o >>= 1) {
            float ov = __shfl_down_sync(0xffffffffu, best, o);
            int oi = __shfl_down_sync(0xffffffffu, bidx, o);
            if (ov > best || (ov == best && oi < bidx)) { best = ov; bidx = oi; }
        }
        bidx = __shfl_sync(0xffffffffu, bidx, 0);
        if (lane == 0) idxo[(long)row * KNN + it] = bidx;
        if ((bidx & 31) == lane) {
            int jw = bidx >> 5;
#pragma unroll
            for (int j = 0; j < 64; j++)
                if (j == jw) r[j] = -INFINITY;
        }
    }
}

// ---------------- build effective edge weights (fp32, layer 1) ----------------
__global__ void make_weff(const float* __restrict__ w, int O, int C,
                          float* __restrict__ weff) {
    int i = blockIdx.x * blockDim.x + threadIdx.x;
    if (i >= 2 * O * C) return;
    int row = i / C, c = i % C;
    if (row < O) weff[i] = w[row * 2 * C + c];
    else {
        int o = row - O;
        weff[i] = w[o * 2 * C + C + c] - w[o * 2 * C + c];
    }
}

// ---------------- gather + max + bn + act ----------------
__global__ void gather_max(const float* __restrict__ YZ, int twoO,
                           const int* __restrict__ idxi,
                           const float* __restrict__ bnp,
                           float* __restrict__ out, int ldo, int O) {
    int n = blockIdx.x, b = blockIdx.y, o = threadIdx.x;
    __shared__ int si[KNN];
    if (o < KNN) si[o] = idxi[((long)b * NPTS + n) * KNN + o];
    __syncthreads();
    const float* Yb = YZ + (long)b * NPTS * twoO;
    float m = -INFINITY;
#pragma unroll 4
    for (int k = 0; k < KNN; k++) m = fmaxf(m, Yb[(long)si[k] * twoO + o]);
    float z = Yb[(long)n * twoO + O + o];
    float t = m + z;
    float gg = bnp[o], be = bnp[O + o], mm = bnp[2 * O + o], vv = bnp[3 * O + o];
    float v = (t - mm) * (gg * rsqrtf(vv + EPS)) + be;
    v = v > 0.f ? v : SLOPE * v;
    out[((long)b * NPTS + n) * ldo + o] = v;
}

// ---------------- small FC ----------------
__global__ void fc_kernel(const float* __restrict__ in, int K,
                          const float* __restrict__ W,
                          const float* __restrict__ bias,
                          const float* __restrict__ bnp, int useAct,
                          float* __restrict__ out, int O) {
    int o = blockIdx.x, b = blockIdx.y, t = threadIdx.x;
    const float* xr = in + (long)b * K;
    const float* wr = W + (long)o * K;
    float s = 0.f;
    for (int k = t; k < K; k += 128) s += xr[k] * wr[k];
    __shared__ float red[4];
#pragma unroll
    for (int off = 16; off; off >>= 1) s += __shfl_down_sync(0xffffffffu, s, off);
    if ((t & 31) == 0) red[t >> 5] = s;
    __syncthreads();
    if (t == 0) {
        float tot = red[0] + red[1] + red[2] + red[3];
        if (bias) tot += bias[o];
        if (bnp) {
            float gg = bnp[o], be = bnp[O + o], mm = bnp[2 * O + o], vv = bnp[3 * O + o];
            tot = (tot - mm) * (gg * rsqrtf(vv + EPS)) + be;
        }
        if (useAct) tot = tot > 0.f ? tot : SLOPE * tot;
        out[(long)b * O + o] = tot;
    }
}

extern "C" void kernel_launch(void* const* d_in, const int* in_sizes, int n_in,
                              void* d_out, int out_size) {
    const float* x   = (const float*)d_in[0];
    const float* w1  = (const float*)d_in[2];
    const float* w2  = (const float*)d_in[3];
    const float* w3  = (const float*)d_in[4];
    const float* w4  = (const float*)d_in[5];
    const float* w5  = (const float*)d_in[6];
    const float* wl1 = (const float*)d_in[7];
    const float* wl2 = (const float*)d_in[8];
    const float* bl2 = (const float*)d_in[9];
    const float* wl3 = (const float*)d_in[10];
    const float* bl3 = (const float*)d_in[11];
    const float* bn1 = (const float*)d_in[12];
    const float* bn2 = (const float*)d_in[13];
    const float* bn3 = (const float*)d_in[14];
    const float* bn4 = (const float*)d_in[15];
    const float* bn5 = (const float*)d_in[16];
    const float* bn6 = (const float*)d_in[17];
    const float* bn7 = (const float*)d_in[18];

    float *S, *d2, *YZ, *xc, *weff, *pmax, *psum, *gb, *h1, *h2;
    int* idx;
    unsigned short *Xh, *Xl, *XCh, *XCl, *W5h, *W5l, *Wh, *Wl;
    cudaGetSymbolAddress((void**)&S, g_S);
    cudaGetSymbolAddress((void**)&d2, g_d2);
    cudaGetSymbolAddress((void**)&idx, g_idx);
    cudaGetSymbolAddress((void**)&YZ, g_YZ);
    cudaGetSymbolAddress((void**)&xc, g_xc);
    cudaGetSymbolAddress((void**)&weff, g_weff);
    cudaGetSymbolAddress((void**)&pmax, g_pmax);
    cudaGetSymbolAddress((void**)&psum, g_psum);
    cudaGetSymbolAddress((void**)&gb, g_g);
    cudaGetSymbolAddress((void**)&h1, g_h1);
    cudaGetSymbolAddress((void**)&h2, g_h2);
    cudaGetSymbolAddress((void**)&Xh, g_Xh);
    cudaGetSymbolAddress((void**)&Xl, g_Xl);
    cudaGetSymbolAddress((void**)&XCh, g_XCh);
    cudaGetSymbolAddress((void**)&XCl, g_XCl);
    cudaGetSymbolAddress((void**)&W5h, g_W5h);
    cudaGetSymbolAddress((void**)&W5l, g_W5l);
    cudaGetSymbolAddress((void**)&Wh, g_Wh);
    cudaGetSymbolAddress((void**)&Wl, g_Wl);

    cudaFuncSetAttribute(gemm_mma, cudaFuncAttributeMaxDynamicSharedMemorySize, GSM_TOTAL);

    const int TOTAL = BSZ * NPTS;  // 16384

    // ---------- layer 1 (exact fp32; K=3) ----------
    d2_kernel<<<TOTAL / 256, 256>>>(x, 3, 3, d2, TOTAL);
    gemm_abT<<<dim3(NPTS / BN, NPTS / BM, BSZ), 256>>>(
        x, 3, (long)NPTS * 3, x, 3, (long)NPTS * 3,
        S, NPTS, (long)NPTS * NPTS, NPTS, NPTS, 3, d2, NPTS, 1);
    topk_kernel<<<TOTAL / 8, 256>>>(S, idx);
    make_weff<<<(2 * 64 * 3 + 255) / 256, 256>>>(w1, 64, 3, weff);
    gemm_abT<<<dim3(1, TOTAL / BM, 1), 256>>>(
        x, 3, 0, weff, 3, 0, YZ, 128, 0, TOTAL, 128, 3, nullptr, 0, 0);
    gather_max<<<dim3(NPTS, BSZ), 64>>>(YZ, 128, idx, bn1, xc + 0, 512, 64);

    // ---------- layers 2-4 (HMMA fp16-split) ----------
    struct L { int off, C, O; const float* w; const float* bn; };
    L Ls[3] = { {0, 64, 64, w2, bn2}, {64, 64, 128, w3, bn3}, {128, 128, 256, w4, bn4} };
    for (int l = 0; l < 3; l++) {
        const L& c = Ls[l];
        d2split_kernel<<<TOTAL / 8, 256>>>(xc + c.off, 512, c.C, TOTAL, Xh, Xl, d2);
        gemm_mma<<<dim3(16, 16, BSZ), 256, GSM_TOTAL>>>(
            Xh, Xl, (long)NPTS * c.C, Xh, Xl, (long)NPTS * c.C,
            S, NPTS, (long)NPTS * NPTS, c.C, d2, nullptr, NPTS, 1, nullptr, nullptr);
        topk_kernel<<<TOTAL / 8, 256>>>(S, idx);
        make_weff_split<<<(2 * c.O * c.C + 255) / 256, 256>>>(c.w, c.O, c.C, Wh, Wl);
        gemm_mma<<<dim3(2 * c.O / 128, TOTAL / 128, 1), 256, GSM_TOTAL>>>(
            Xh, Xl, 0, Wh, Wl, 0,
            YZ, 2 * c.O, 0, c.C, nullptr, nullptr, 2 * c.O, 0, nullptr, nullptr);
        int outoff = (l == 0) ? 64 : (l == 1) ? 128 : 256;
        gather_max<<<dim3(NPTS, BSZ), c.O>>>(YZ, 2 * c.O, idx, c.bn, xc + outoff, 512, c.O);
    }

    // ---------- x5 GEMM with fused pool partials ----------
    d2split_kernel<<<TOTAL / 8, 256>>>(xc, 512, 512, TOTAL, XCh, XCl, nullptr);
    d2split_kernel<<<1024 / 8, 256>>>(w5, 512, 512, 1024, W5h, W5l, nullptr);
    gemm_mma<<<dim3(8, TOTAL / 128, 1), 256, GSM_TOTAL>>>(
        XCh, XCl, 0, W5h, W5l, 0,
        nullptr, 1024, 0, 512, nullptr, bn5, 1024, 3, pmax, psum);
    pool_reduce<<<dim3(4, BSZ), 256>>>(pmax, psum, gb);

    // ---------- FC stack ----------
    fc_kernel<<<dim3(512, BSZ), 128>>>(gb, 2048, wl1, nullptr, bn6, 1, h1, 512);
    fc_kernel<<<dim3(256, BSZ), 128>>>(h1, 512, wl2, bl2, bn7, 1, h2, 256);
    fc_kernel<<<dim3(40, BSZ), 128>>>(h2, 256, wl3, bl3, nullptr, 0, (float*)d_out, 40);
}